// round 1
// baseline (speedup 1.0000x reference)
#include <cuda_runtime.h>

// Problem constants
#define BB  2
#define SS  2048
#define DD  1024
#define HH  16
#define DKK 64
#define MM  (BB*SS)   // 4096 rows

// Scratch (allocation-free rule: __device__ globals)
__device__ float g_Q[(size_t)MM*DD];
__device__ float g_K[(size_t)MM*DD];
__device__ float g_V[(size_t)MM*DD];
__device__ float g_O[(size_t)MM*DD];

// ---------------------------------------------------------------------------
// GEMM (NT): C[m][n] = sum_k A[m][k] * W[n][k] + bias[n]
// A: (M,K) row-major, W: (N,K) row-major (torch Linear weight layout)
// Tile 64x64, BK=32, 256 threads, 4x4 per thread.
// Smem stored k-major ([k][m]) so the inner loop reads conflict-free float4s.
// ---------------------------------------------------------------------------
__global__ __launch_bounds__(256) void gemm_nt_bias(
    const float* __restrict__ A, const float* __restrict__ W,
    const float* __restrict__ bias, float* __restrict__ C,
    int Mdim, int Ndim, int Kdim)
{
    __shared__ float At[32][68];   // [k][m], padded stride 68 (16B-aligned rows)
    __shared__ float Wt[32][68];   // [k][n]

    const int tid = threadIdx.x;
    const int tx = tid & 15;
    const int ty = tid >> 4;
    const int m0 = blockIdx.y * 64;
    const int n0 = blockIdx.x * 64;

    float acc[4][4] = {};

    for (int k0 = 0; k0 < Kdim; k0 += 32) {
        // Load 64 rows x 32 k of A and W, transposed into smem.
        #pragma unroll
        for (int it = 0; it < 2; it++) {
            int idx  = tid + it * 256;       // 0..511
            int row  = idx >> 3;             // 0..63
            int quad = idx & 7;              // 0..7 (k/4)
            float4 a = *(const float4*)(A + (size_t)(m0 + row) * Kdim + k0 + quad * 4);
            At[quad*4+0][row] = a.x; At[quad*4+1][row] = a.y;
            At[quad*4+2][row] = a.z; At[quad*4+3][row] = a.w;
            float4 w = *(const float4*)(W + (size_t)(n0 + row) * Kdim + k0 + quad * 4);
            Wt[quad*4+0][row] = w.x; Wt[quad*4+1][row] = w.y;
            Wt[quad*4+2][row] = w.z; Wt[quad*4+3][row] = w.w;
        }
        __syncthreads();

        #pragma unroll 16
        for (int kk = 0; kk < 32; kk++) {
            float4 av = *(const float4*)&At[kk][ty * 4];
            float4 wv = *(const float4*)&Wt[kk][tx * 4];
            float a4[4] = {av.x, av.y, av.z, av.w};
            float w4[4] = {wv.x, wv.y, wv.z, wv.w};
            #pragma unroll
            for (int i = 0; i < 4; i++)
                #pragma unroll
                for (int j = 0; j < 4; j++)
                    acc[i][j] += a4[i] * w4[j];
        }
        __syncthreads();
    }

    float4 bv = *(const float4*)(bias + n0 + tx * 4);
    #pragma unroll
    for (int i = 0; i < 4; i++) {
        int m = m0 + ty * 4 + i;
        float4 o;
        o.x = acc[i][0] + bv.x;
        o.y = acc[i][1] + bv.y;
        o.z = acc[i][2] + bv.z;
        o.w = acc[i][3] + bv.w;
        *(float4*)(C + (size_t)m * Ndim + n0 + tx * 4) = o;
    }
}

// ---------------------------------------------------------------------------
// Flash attention (causal), fp32, online softmax.
// Block: 64 queries x one (b,h). 256 threads = 16x16, 4x4 scores per thread.
// Qt/Kt stored [d][row] transposed for conflict-free float4 inner-product loads.
// P is written back into the Kt region (reloaded next tile) -> 48KB static smem.
// ---------------------------------------------------------------------------
__global__ __launch_bounds__(256) void attn_flash(
    const float* __restrict__ Qp, const float* __restrict__ Kp,
    const float* __restrict__ Vp, float* __restrict__ Op)
{
    __shared__ float Qt[64][64];   // [d][q]
    __shared__ float Kt[64][64];   // [d][k]; aliased as P[q*64+k] after scores
    __shared__ float Vs[64][64];   // [k][d]

    const int tid = threadIdx.x;
    const int tx  = tid & 15;
    const int ty  = tid >> 4;
    const int qb  = blockIdx.x;          // query block
    const int bh  = blockIdx.y;          // b*H + h
    const int b   = bh >> 4;
    const int h   = bh & 15;

    const size_t rowbase = (size_t)b * SS;
    const int col0 = h * DKK;

    // Load Q tile transposed: Qt[d][q]
    #pragma unroll
    for (int it = 0; it < 4; it++) {
        int idx  = tid + it * 256;       // 0..1023
        int row  = idx >> 4;             // 0..63 (query)
        int quad = idx & 15;             // 0..15 (d/4)
        float4 qv = *(const float4*)(Qp + (rowbase + (size_t)qb*64 + row) * DD + col0 + quad * 4);
        Qt[quad*4+0][row] = qv.x; Qt[quad*4+1][row] = qv.y;
        Qt[quad*4+2][row] = qv.z; Qt[quad*4+3][row] = qv.w;
    }

    float m_run[4], l_run[4], out[4][4];
    #pragma unroll
    for (int i = 0; i < 4; i++) {
        m_run[i] = -1e30f;
        l_run[i] = 0.f;
        #pragma unroll
        for (int j = 0; j < 4; j++) out[i][j] = 0.f;
    }

    for (int kb = 0; kb <= qb; kb++) {
        __syncthreads();   // prior iter done with Kt(P)/Vs; also fences Q stores (iter 0)

        // Load K tile transposed + V tile natural
        #pragma unroll
        for (int it = 0; it < 4; it++) {
            int idx  = tid + it * 256;
            int row  = idx >> 4;
            int quad = idx & 15;
            size_t g = (rowbase + (size_t)kb*64 + row) * DD + col0 + quad * 4;
            float4 kv = *(const float4*)(Kp + g);
            Kt[quad*4+0][row] = kv.x; Kt[quad*4+1][row] = kv.y;
            Kt[quad*4+2][row] = kv.z; Kt[quad*4+3][row] = kv.w;
            float4 vv = *(const float4*)(Vp + g);
            *(float4*)&Vs[row][quad*4] = vv;
        }
        __syncthreads();

        // Scores: s[i][j] = Q[qrow] . K[krow]
        float s[4][4] = {};
        #pragma unroll 8
        for (int d = 0; d < 64; d++) {
            float4 qv = *(const float4*)&Qt[d][ty * 4];
            float4 kv = *(const float4*)&Kt[d][tx * 4];
            float q4[4] = {qv.x, qv.y, qv.z, qv.w};
            float k4[4] = {kv.x, kv.y, kv.z, kv.w};
            #pragma unroll
            for (int i = 0; i < 4; i++)
                #pragma unroll
                for (int j = 0; j < 4; j++)
                    s[i][j] += q4[i] * k4[j];
        }

        // Scale + causal mask (diagonal tile only)
        const bool diag = (kb == qb);
        #pragma unroll
        for (int i = 0; i < 4; i++)
            #pragma unroll
            for (int j = 0; j < 4; j++) {
                s[i][j] *= 0.125f;   // 1/sqrt(64)
                if (diag && (tx * 4 + j > ty * 4 + i)) s[i][j] = -1e30f;
            }

        // Online softmax (row spread across 16 lanes)
        float p[4][4];
        #pragma unroll
        for (int i = 0; i < 4; i++) {
            float tm = fmaxf(fmaxf(s[i][0], s[i][1]), fmaxf(s[i][2], s[i][3]));
            #pragma unroll
            for (int off = 8; off; off >>= 1)
                tm = fmaxf(tm, __shfl_xor_sync(0xffffffffu, tm, off));
            float mn  = fmaxf(m_run[i], tm);
            float fac = __expf(m_run[i] - mn);
            m_run[i]  = mn;
            float rs = 0.f;
            #pragma unroll
            for (int j = 0; j < 4; j++) {
                p[i][j] = __expf(s[i][j] - mn);
                rs += p[i][j];
            }
            #pragma unroll
            for (int off = 8; off; off >>= 1)
                rs += __shfl_xor_sync(0xffffffffu, rs, off);
            l_run[i] = l_run[i] * fac + rs;
            #pragma unroll
            for (int j = 0; j < 4; j++) out[i][j] *= fac;
        }

        __syncthreads();   // everyone done reading Kt
        float* P = &Kt[0][0];
        #pragma unroll
        for (int i = 0; i < 4; i++)
            #pragma unroll
            for (int j = 0; j < 4; j++)
                P[(ty * 4 + i) * 64 + tx * 4 + j] = p[i][j];
        __syncthreads();

        // out += P @ V
        #pragma unroll 8
        for (int kk = 0; kk < 64; kk++) {
            float4 vv = *(const float4*)&Vs[kk][tx * 4];
            float v4[4] = {vv.x, vv.y, vv.z, vv.w};
            #pragma unroll
            for (int i = 0; i < 4; i++) {
                float pi = P[(ty * 4 + i) * 64 + kk];
                #pragma unroll
                for (int j = 0; j < 4; j++)
                    out[i][j] += pi * v4[j];
            }
        }
    }

    // Normalize and write O (merged-head layout (B,S,D))
    #pragma unroll
    for (int i = 0; i < 4; i++) {
        float inv = 1.f / l_run[i];
        float4 o;
        o.x = out[i][0] * inv;
        o.y = out[i][1] * inv;
        o.z = out[i][2] * inv;
        o.w = out[i][3] * inv;
        *(float4*)(Op + (rowbase + (size_t)qb*64 + ty*4 + i) * DD + col0 + tx * 4) = o;
    }
}

// ---------------------------------------------------------------------------
// Launch: Qproj, Kproj, Vproj -> attention -> Oproj
// Inputs (metadata order): q,k,v,mask,wq,bq,wk,bk,wv,bv,wo,bo
// mask is the causal tril by construction -> implemented as causal predicate.
// ---------------------------------------------------------------------------
extern "C" void kernel_launch(void* const* d_in, const int* in_sizes, int n_in,
                              void* d_out, int out_size)
{
    const float* q  = (const float*)d_in[0];
    const float* k  = (const float*)d_in[1];
    const float* v  = (const float*)d_in[2];
    const float* wq = (const float*)d_in[4];
    const float* bq = (const float*)d_in[5];
    const float* wk = (const float*)d_in[6];
    const float* bk = (const float*)d_in[7];
    const float* wv = (const float*)d_in[8];
    const float* bv = (const float*)d_in[9];
    const float* wo = (const float*)d_in[10];
    const float* bo = (const float*)d_in[11];

    float *Qp, *Kp, *Vp, *Opp;
    cudaGetSymbolAddress((void**)&Qp,  g_Q);
    cudaGetSymbolAddress((void**)&Kp,  g_K);
    cudaGetSymbolAddress((void**)&Vp,  g_V);
    cudaGetSymbolAddress((void**)&Opp, g_O);

    dim3 gemmGrid(DD / 64, MM / 64);   // (16, 64)
    dim3 attnGrid(SS / 64, BB * HH);   // (32, 32)

    gemm_nt_bias<<<gemmGrid, 256>>>(q, wq, bq, Qp, MM, DD, DD);
    gemm_nt_bias<<<gemmGrid, 256>>>(k, wk, bk, Kp, MM, DD, DD);
    gemm_nt_bias<<<gemmGrid, 256>>>(v, wv, bv, Vp, MM, DD, DD);
    attn_flash<<<attnGrid, 256>>>(Qp, Kp, Vp, Opp);
    gemm_nt_bias<<<gemmGrid, 256>>>(Opp, wo, bo, (float*)d_out, MM, DD, DD);
}

// round 6
// speedup vs baseline: 1.4677x; 1.4677x over previous
#include <cuda_runtime.h>
#include <cuda_bf16.h>
#include <cstdint>

// Problem constants
#define BB  2
#define SS  2048
#define DD  1024
#define HH  16
#define DKK 64
#define MM  (BB*SS)   // 4096 rows

#define ELEMS_IN ((size_t)MM*DD)   // 4194304
#define ELEMS_W  ((size_t)DD*DD)   // 1048576

// Offsets (elements) inside the shared hi/lo bf16 scratch
#define OFF_Q  ((size_t)0)
#define OFF_K  (ELEMS_IN)
#define OFF_V  (2*ELEMS_IN)
#define OFF_O  (3*ELEMS_IN)
#define OFF_WQ (4*ELEMS_IN)
#define OFF_WK (4*ELEMS_IN + ELEMS_W)
#define OFF_WV (4*ELEMS_IN + 2*ELEMS_W)
#define OFF_WO (4*ELEMS_IN + 3*ELEMS_W)

// Scratch (allocation-free rule: __device__ globals)
__device__ float g_Q[ELEMS_IN];
__device__ float g_K[ELEMS_IN];
__device__ float g_V[ELEMS_IN];
__device__ float g_O[ELEMS_IN];
__device__ __nv_bfloat16 g_hi[4*ELEMS_IN + 4*ELEMS_W];
__device__ __nv_bfloat16 g_lo[4*ELEMS_IN + 4*ELEMS_W];

// ---------------------------------------------------------------------------
// helpers
// ---------------------------------------------------------------------------
__device__ __forceinline__ uint32_t smem_u32(const void* p) {
    uint32_t a;
    asm("{ .reg .u64 t; cvta.to.shared.u64 t, %1; cvt.u32.u64 %0, t; }"
        : "=r"(a) : "l"(p));
    return a;
}

__device__ __forceinline__ void ldmatrix_x4(uint32_t* r, uint32_t addr) {
    asm volatile("ldmatrix.sync.aligned.m8n8.x4.shared.b16 {%0,%1,%2,%3}, [%4];"
                 : "=r"(r[0]), "=r"(r[1]), "=r"(r[2]), "=r"(r[3]) : "r"(addr));
}

__device__ __forceinline__ void mma_bf16(float* c, const uint32_t* a,
                                         const uint32_t* b) {
    asm volatile(
        "mma.sync.aligned.m16n8k16.row.col.f32.bf16.bf16.f32 "
        "{%0,%1,%2,%3}, {%4,%5,%6,%7}, {%8,%9}, {%0,%1,%2,%3};"
        : "+f"(c[0]), "+f"(c[1]), "+f"(c[2]), "+f"(c[3])
        : "r"(a[0]), "r"(a[1]), "r"(a[2]), "r"(a[3]), "r"(b[0]), "r"(b[1]));
}

// ---------------------------------------------------------------------------
// fp32 -> (bf16 hi, bf16 lo) split, vectorized x4.
// hi = truncate-to-bf16 (top 16 bits), lo = rn(a - hi)  =>  a ~= hi + lo
// ---------------------------------------------------------------------------
__global__ __launch_bounds__(256) void split_bf16(
    const float* __restrict__ in, __nv_bfloat16* __restrict__ hi,
    __nv_bfloat16* __restrict__ lo, int n4)
{
    int i = blockIdx.x * blockDim.x + threadIdx.x;
    if (i >= n4) return;
    float4 a = ((const float4*)in)[i];
    uint32_t b0 = __float_as_uint(a.x), b1 = __float_as_uint(a.y);
    uint32_t b2 = __float_as_uint(a.z), b3 = __float_as_uint(a.w);
    uint2 h;
    h.x = (b0 >> 16) | (b1 & 0xffff0000u);
    h.y = (b2 >> 16) | (b3 & 0xffff0000u);
    float l0 = a.x - __uint_as_float(b0 & 0xffff0000u);
    float l1 = a.y - __uint_as_float(b1 & 0xffff0000u);
    float l2 = a.z - __uint_as_float(b2 & 0xffff0000u);
    float l3 = a.w - __uint_as_float(b3 & 0xffff0000u);
    __nv_bfloat162 p0 = __floats2bfloat162_rn(l0, l1);
    __nv_bfloat162 p1 = __floats2bfloat162_rn(l2, l3);
    uint2 lw;
    lw.x = *(uint32_t*)&p0;
    lw.y = *(uint32_t*)&p1;
    ((uint2*)hi)[i] = h;
    ((uint2*)lo)[i] = lw;
}

// ---------------------------------------------------------------------------
// HMMA bf16x3 GEMM (NT): C[m][n] = sum_k A[m][k]*W[n][k] + bias[n]
// A,W pre-split (hi,lo) bf16 K-major. Block 128x128, BK=32, 256 threads.
// Warp grid 2(m) x 4(n): warp tile 64x32. mma.sync m16n8k16, 3 terms.
// Smem rows padded to 40 bf16 (80B) -> conflict-free ldmatrix.
// Each thread stores 2x uint4 (32B) per array => full 64B row coverage.
// ---------------------------------------------------------------------------
#define KSTR 40

__global__ __launch_bounds__(256) void gemm_hmma(
    const __nv_bfloat16* __restrict__ Ahi, const __nv_bfloat16* __restrict__ Alo,
    const __nv_bfloat16* __restrict__ Whi, const __nv_bfloat16* __restrict__ Wlo,
    const float* __restrict__ bias, float* __restrict__ C)
{
    __shared__ __align__(16) __nv_bfloat16 sAh[128 * KSTR], sAl[128 * KSTR];
    __shared__ __align__(16) __nv_bfloat16 sWh[128 * KSTR], sWl[128 * KSTR];

    const int tid  = threadIdx.x;
    const int warp = tid >> 5;
    const int lane = tid & 31;
    const int wm   = warp & 1;        // 0..1  -> 64 rows of M
    const int wn   = warp >> 1;       // 0..3  -> 32 cols of N
    const int m0   = blockIdx.y * 128;
    const int n0   = blockIdx.x * 128;

    const uint32_t sAh_b = smem_u32(sAh), sAl_b = smem_u32(sAl);
    const uint32_t sWh_b = smem_u32(sWh), sWl_b = smem_u32(sWl);

    float acc[4][4][4] = {};          // [im][in][e]

    const int lrow = tid >> 1;        // 0..127
    const int lcol = (tid & 1) * 16;  // element 0 or 16 (each thread: 16 elems)
    const uint32_t s_off = (uint32_t)(lrow * KSTR + lcol) * 2;

    // ldmatrix source offsets (within A/W tiles)
    const int fr = lane & 15;
    const int fc = (lane >> 4) * 8;
    const uint32_t a_off = (uint32_t)((wm * 64 + fr) * KSTR + fc) * 2;
    const uint32_t b_off = (uint32_t)((wn * 32 + fr) * KSTR + fc) * 2;

    for (int k0 = 0; k0 < DD; k0 += 32) {
        const size_t ga = (size_t)(m0 + lrow) * DD + k0 + lcol;
        const size_t gw = (size_t)(n0 + lrow) * DD + k0 + lcol;
        *(uint4*)((char*)sAh + s_off)      = *(const uint4*)(Ahi + ga);
        *(uint4*)((char*)sAh + s_off + 16) = *(const uint4*)(Ahi + ga + 8);
        *(uint4*)((char*)sAl + s_off)      = *(const uint4*)(Alo + ga);
        *(uint4*)((char*)sAl + s_off + 16) = *(const uint4*)(Alo + ga + 8);
        *(uint4*)((char*)sWh + s_off)      = *(const uint4*)(Whi + gw);
        *(uint4*)((char*)sWh + s_off + 16) = *(const uint4*)(Whi + gw + 8);
        *(uint4*)((char*)sWl + s_off)      = *(const uint4*)(Wlo + gw);
        *(uint4*)((char*)sWl + s_off + 16) = *(const uint4*)(Wlo + gw + 8);
        __syncthreads();

        #pragma unroll
        for (int ks = 0; ks < 2; ks++) {
            const uint32_t ko = (uint32_t)(ks * 16) * 2;
            uint32_t ah[4][4], al[4][4];
            #pragma unroll
            for (int im = 0; im < 4; im++) {
                const uint32_t ro = (uint32_t)(im * 16 * KSTR) * 2;
                ldmatrix_x4(ah[im], sAh_b + a_off + ro + ko);
                ldmatrix_x4(al[im], sAl_b + a_off + ro + ko);
            }
            uint32_t bh[4][2], bl[4][2];
            #pragma unroll
            for (int p = 0; p < 2; p++) {
                const uint32_t ro = (uint32_t)(p * 16 * KSTR) * 2;
                uint32_t t[4];
                ldmatrix_x4(t, sWh_b + b_off + ro + ko);
                bh[2*p][0] = t[0]; bh[2*p][1] = t[2];
                bh[2*p+1][0] = t[1]; bh[2*p+1][1] = t[3];
                ldmatrix_x4(t, sWl_b + b_off + ro + ko);
                bl[2*p][0] = t[0]; bl[2*p][1] = t[2];
                bl[2*p+1][0] = t[1]; bl[2*p+1][1] = t[3];
            }
            #pragma unroll
            for (int im = 0; im < 4; im++)
                #pragma unroll
                for (int in = 0; in < 4; in++) {
                    mma_bf16(acc[im][in], ah[im], bh[in]);
                    mma_bf16(acc[im][in], ah[im], bl[in]);
                    mma_bf16(acc[im][in], al[im], bh[in]);
                }
        }
        __syncthreads();
    }

    // Epilogue: c layout m16n8 -> thread holds (r, 2c),(r,2c+1),(r+8,2c),(r+8,2c+1)
    const int tr = lane >> 2;         // 0..7
    const int tc = (lane & 3) * 2;    // 0,2,4,6
    #pragma unroll
    for (int im = 0; im < 4; im++) {
        #pragma unroll
        for (int in = 0; in < 4; in++) {
            const int m = m0 + wm * 64 + im * 16 + tr;
            const int n = n0 + wn * 32 + in * 8 + tc;
            const float bx = bias[n], by = bias[n + 1];
            float2 v0 = make_float2(acc[im][in][0] + bx, acc[im][in][1] + by);
            float2 v1 = make_float2(acc[im][in][2] + bx, acc[im][in][3] + by);
            *(float2*)(C + (size_t)m * DD + n) = v0;
            *(float2*)(C + (size_t)(m + 8) * DD + n) = v1;
        }
    }
}

// ---------------------------------------------------------------------------
// Flash attention (causal), fp32, online softmax. (unchanged from R1)
// ---------------------------------------------------------------------------
__global__ __launch_bounds__(256) void attn_flash(
    const float* __restrict__ Qp, const float* __restrict__ Kp,
    const float* __restrict__ Vp, float* __restrict__ Op)
{
    __shared__ float Qt[64][64];   // [d][q]
    __shared__ float Kt[64][64];   // [d][k]; aliased as P[q*64+k] after scores
    __shared__ float Vs[64][64];   // [k][d]

    const int tid = threadIdx.x;
    const int tx  = tid & 15;
    const int ty  = tid >> 4;
    const int qb  = blockIdx.x;
    const int bh  = blockIdx.y;
    const int b   = bh >> 4;
    const int h   = bh & 15;

    const size_t rowbase = (size_t)b * SS;
    const int col0 = h * DKK;

    #pragma unroll
    for (int it = 0; it < 4; it++) {
        int idx  = tid + it * 256;
        int row  = idx >> 4;
        int quad = idx & 15;
        float4 qv = *(const float4*)(Qp + (rowbase + (size_t)qb*64 + row) * DD + col0 + quad * 4);
        Qt[quad*4+0][row] = qv.x; Qt[quad*4+1][row] = qv.y;
        Qt[quad*4+2][row] = qv.z; Qt[quad*4+3][row] = qv.w;
    }

    float m_run[4], l_run[4], out[4][4];
    #pragma unroll
    for (int i = 0; i < 4; i++) {
        m_run[i] = -1e30f;
        l_run[i] = 0.f;
        #pragma unroll
        for (int j = 0; j < 4; j++) out[i][j] = 0.f;
    }

    for (int kb = 0; kb <= qb; kb++) {
        __syncthreads();

        #pragma unroll
        for (int it = 0; it < 4; it++) {
            int idx  = tid + it * 256;
            int row  = idx >> 4;
            int quad = idx & 15;
            size_t g = (rowbase + (size_t)kb*64 + row) * DD + col0 + quad * 4;
            float4 kv = *(const float4*)(Kp + g);
            Kt[quad*4+0][row] = kv.x; Kt[quad*4+1][row] = kv.y;
            Kt[quad*4+2][row] = kv.z; Kt[quad*4+3][row] = kv.w;
            float4 vv = *(const float4*)(Vp + g);
            *(float4*)&Vs[row][quad*4] = vv;
        }
        __syncthreads();

        float s[4][4] = {};
        #pragma unroll 8
        for (int d = 0; d < 64; d++) {
            float4 qv = *(const float4*)&Qt[d][ty * 4];
            float4 kv = *(const float4*)&Kt[d][tx * 4];
            float q4[4] = {qv.x, qv.y, qv.z, qv.w};
            float k4[4] = {kv.x, kv.y, kv.z, kv.w};
            #pragma unroll
            for (int i = 0; i < 4; i++)
                #pragma unroll
                for (int j = 0; j < 4; j++)
                    s[i][j] += q4[i] * k4[j];
        }

        const bool diag = (kb == qb);
        #pragma unroll
        for (int i = 0; i < 4; i++)
            #pragma unroll
            for (int j = 0; j < 4; j++) {
                s[i][j] *= 0.125f;
                if (diag && (tx * 4 + j > ty * 4 + i)) s[i][j] = -1e30f;
            }

        float p[4][4];
        #pragma unroll
        for (int i = 0; i < 4; i++) {
            float tm = fmaxf(fmaxf(s[i][0], s[i][1]), fmaxf(s[i][2], s[i][3]));
            #pragma unroll
            for (int off = 8; off; off >>= 1)
                tm = fmaxf(tm, __shfl_xor_sync(0xffffffffu, tm, off));
            float mn  = fmaxf(m_run[i], tm);
            float fac = __expf(m_run[i] - mn);
            m_run[i]  = mn;
            float rs = 0.f;
            #pragma unroll
            for (int j = 0; j < 4; j++) {
                p[i][j] = __expf(s[i][j] - mn);
                rs += p[i][j];
            }
            #pragma unroll
            for (int off = 8; off; off >>= 1)
                rs += __shfl_xor_sync(0xffffffffu, rs, off);
            l_run[i] = l_run[i] * fac + rs;
            #pragma unroll
            for (int j = 0; j < 4; j++) out[i][j] *= fac;
        }

        __syncthreads();
        float* P = &Kt[0][0];
        #pragma unroll
        for (int i = 0; i < 4; i++)
            #pragma unroll
            for (int j = 0; j < 4; j++)
                P[(ty * 4 + i) * 64 + tx * 4 + j] = p[i][j];
        __syncthreads();

        #pragma unroll 8
        for (int kk = 0; kk < 64; kk++) {
            float4 vv = *(const float4*)&Vs[kk][tx * 4];
            float v4[4] = {vv.x, vv.y, vv.z, vv.w};
            #pragma unroll
            for (int i = 0; i < 4; i++) {
                float pi = P[(ty * 4 + i) * 64 + kk];
                #pragma unroll
                for (int j = 0; j < 4; j++)
                    out[i][j] += pi * v4[j];
            }
        }
    }

    #pragma unroll
    for (int i = 0; i < 4; i++) {
        float inv = 1.f / l_run[i];
        float4 o;
        o.x = out[i][0] * inv;
        o.y = out[i][1] * inv;
        o.z = out[i][2] * inv;
        o.w = out[i][3] * inv;
        *(float4*)(Op + (rowbase + (size_t)qb*64 + ty*4 + i) * DD + col0 + tx * 4) = o;
    }
}

// ---------------------------------------------------------------------------
// Launch. Inputs (metadata order): q,k,v,mask,wq,bq,wk,bk,wv,bv,wo,bo
// ---------------------------------------------------------------------------
extern "C" void kernel_launch(void* const* d_in, const int* in_sizes, int n_in,
                              void* d_out, int out_size)
{
    const float* q  = (const float*)d_in[0];
    const float* k  = (const float*)d_in[1];
    const float* v  = (const float*)d_in[2];
    const float* wq = (const float*)d_in[4];
    const float* bq = (const float*)d_in[5];
    const float* wk = (const float*)d_in[6];
    const float* bk = (const float*)d_in[7];
    const float* wv = (const float*)d_in[8];
    const float* bv = (const float*)d_in[9];
    const float* wo = (const float*)d_in[10];
    const float* bo = (const float*)d_in[11];

    float *Qp, *Kp, *Vp, *Opp;
    __nv_bfloat16 *hi, *lo;
    cudaGetSymbolAddress((void**)&Qp,  g_Q);
    cudaGetSymbolAddress((void**)&Kp,  g_K);
    cudaGetSymbolAddress((void**)&Vp,  g_V);
    cudaGetSymbolAddress((void**)&Opp, g_O);
    cudaGetSymbolAddress((void**)&hi,  g_hi);
    cudaGetSymbolAddress((void**)&lo,  g_lo);

    const int nin4 = (int)(ELEMS_IN / 4);
    const int nw4  = (int)(ELEMS_W / 4);

    // Split inputs + weights to (hi, lo) bf16
    split_bf16<<<nin4 / 256, 256>>>(q,  hi + OFF_Q,  lo + OFF_Q,  nin4);
    split_bf16<<<nin4 / 256, 256>>>(k,  hi + OFF_K,  lo + OFF_K,  nin4);
    split_bf16<<<nin4 / 256, 256>>>(v,  hi + OFF_V,  lo + OFF_V,  nin4);
    split_bf16<<<nw4  / 256, 256>>>(wq, hi + OFF_WQ, lo + OFF_WQ, nw4);
    split_bf16<<<nw4  / 256, 256>>>(wk, hi + OFF_WK, lo + OFF_WK, nw4);
    split_bf16<<<nw4  / 256, 256>>>(wv, hi + OFF_WV, lo + OFF_WV, nw4);
    split_bf16<<<nw4  / 256, 256>>>(wo, hi + OFF_WO, lo + OFF_WO, nw4);

    dim3 gemmGrid(DD / 128, MM / 128);   // (8, 32)
    gemm_hmma<<<gemmGrid, 256>>>(hi + OFF_Q, lo + OFF_Q, hi + OFF_WQ, lo + OFF_WQ, bq, Qp);
    gemm_hmma<<<gemmGrid, 256>>>(hi + OFF_K, lo + OFF_K, hi + OFF_WK, lo + OFF_WK, bk, Kp);
    gemm_hmma<<<gemmGrid, 256>>>(hi + OFF_V, lo + OFF_V, hi + OFF_WV, lo + OFF_WV, bv, Vp);

    dim3 attnGrid(SS / 64, BB * HH);     // (32, 32)
    attn_flash<<<attnGrid, 256>>>(Qp, Kp, Vp, Opp);

    split_bf16<<<nin4 / 256, 256>>>(Opp, hi + OFF_O, lo + OFF_O, nin4);
    gemm_hmma<<<gemmGrid, 256>>>(hi + OFF_O, lo + OFF_O, hi + OFF_WO, lo + OFF_WO, bo, (float*)d_out);
}

// round 9
// speedup vs baseline: 2.4732x; 1.6851x over previous
#include <cuda_runtime.h>
#include <cuda_bf16.h>
#include <cuda_fp16.h>
#include <cstdint>

// Problem constants
#define BB  2
#define SS  2048
#define DD  1024
#define HH  16
#define DKK 64
#define MM  (BB*SS)   // 4096 rows

#define ELEMS_IN ((size_t)MM*DD)   // 4194304
#define ELEMS_W  ((size_t)DD*DD)   // 1048576

// Offsets (elements) inside the shared hi/lo bf16 scratch
#define OFF_Q  ((size_t)0)
#define OFF_K  (ELEMS_IN)
#define OFF_V  (2*ELEMS_IN)
#define OFF_O  (3*ELEMS_IN)
#define OFF_WQ (4*ELEMS_IN)
#define OFF_WK (4*ELEMS_IN + ELEMS_W)
#define OFF_WV (4*ELEMS_IN + 2*ELEMS_W)
#define OFF_WO (4*ELEMS_IN + 3*ELEMS_W)

// Scratch (allocation-free rule: __device__ globals)
__device__ float g_Q[ELEMS_IN];
__device__ float g_K[ELEMS_IN];
__device__ float g_V[ELEMS_IN];
__device__ float g_O[ELEMS_IN];
__device__ __nv_bfloat16 g_hi[4*ELEMS_IN + 4*ELEMS_W];
__device__ __nv_bfloat16 g_lo[4*ELEMS_IN + 4*ELEMS_W];

// ---------------------------------------------------------------------------
// helpers
// ---------------------------------------------------------------------------
__device__ __forceinline__ uint32_t smem_u32(const void* p) {
    uint32_t a;
    asm("{ .reg .u64 t; cvta.to.shared.u64 t, %1; cvt.u32.u64 %0, t; }"
        : "=r"(a) : "l"(p));
    return a;
}

__device__ __forceinline__ void ldmatrix_x4(uint32_t* r, uint32_t addr) {
    asm volatile("ldmatrix.sync.aligned.m8n8.x4.shared.b16 {%0,%1,%2,%3}, [%4];"
                 : "=r"(r[0]), "=r"(r[1]), "=r"(r[2]), "=r"(r[3]) : "r"(addr));
}

__device__ __forceinline__ void mma_bf16(float* c, const uint32_t* a,
                                         const uint32_t* b) {
    asm volatile(
        "mma.sync.aligned.m16n8k16.row.col.f32.bf16.bf16.f32 "
        "{%0,%1,%2,%3}, {%4,%5,%6,%7}, {%8,%9}, {%0,%1,%2,%3};"
        : "+f"(c[0]), "+f"(c[1]), "+f"(c[2]), "+f"(c[3])
        : "r"(a[0]), "r"(a[1]), "r"(a[2]), "r"(a[3]), "r"(b[0]), "r"(b[1]));
}

__device__ __forceinline__ void mma_f16(float* c, const uint32_t* a,
                                        uint32_t b0, uint32_t b1) {
    asm volatile(
        "mma.sync.aligned.m16n8k16.row.col.f32.f16.f16.f32 "
        "{%0,%1,%2,%3}, {%4,%5,%6,%7}, {%8,%9}, {%0,%1,%2,%3};"
        : "+f"(c[0]), "+f"(c[1]), "+f"(c[2]), "+f"(c[3])
        : "r"(a[0]), "r"(a[1]), "r"(a[2]), "r"(a[3]), "r"(b0), "r"(b1));
}

// ---------------------------------------------------------------------------
// fp32 -> (bf16 hi, bf16 lo) split, vectorized x4.
// ---------------------------------------------------------------------------
__global__ __launch_bounds__(256) void split_bf16(
    const float* __restrict__ in, __nv_bfloat16* __restrict__ hi,
    __nv_bfloat16* __restrict__ lo, int n4)
{
    int i = blockIdx.x * blockDim.x + threadIdx.x;
    if (i >= n4) return;
    float4 a = ((const float4*)in)[i];
    uint32_t b0 = __float_as_uint(a.x), b1 = __float_as_uint(a.y);
    uint32_t b2 = __float_as_uint(a.z), b3 = __float_as_uint(a.w);
    uint2 h;
    h.x = (b0 >> 16) | (b1 & 0xffff0000u);
    h.y = (b2 >> 16) | (b3 & 0xffff0000u);
    float l0 = a.x - __uint_as_float(b0 & 0xffff0000u);
    float l1 = a.y - __uint_as_float(b1 & 0xffff0000u);
    float l2 = a.z - __uint_as_float(b2 & 0xffff0000u);
    float l3 = a.w - __uint_as_float(b3 & 0xffff0000u);
    __nv_bfloat162 p0 = __floats2bfloat162_rn(l0, l1);
    __nv_bfloat162 p1 = __floats2bfloat162_rn(l2, l3);
    uint2 lw;
    lw.x = *(uint32_t*)&p0;
    lw.y = *(uint32_t*)&p1;
    ((uint2*)hi)[i] = h;
    ((uint2*)lo)[i] = lw;
}

// ---------------------------------------------------------------------------
// HMMA bf16x3 GEMM (NT) — unchanged from R6 (verified).
// ---------------------------------------------------------------------------
#define KSTR 40

__global__ __launch_bounds__(256) void gemm_hmma(
    const __nv_bfloat16* __restrict__ Ahi, const __nv_bfloat16* __restrict__ Alo,
    const __nv_bfloat16* __restrict__ Whi, const __nv_bfloat16* __restrict__ Wlo,
    const float* __restrict__ bias, float* __restrict__ C)
{
    __shared__ __align__(16) __nv_bfloat16 sAh[128 * KSTR], sAl[128 * KSTR];
    __shared__ __align__(16) __nv_bfloat16 sWh[128 * KSTR], sWl[128 * KSTR];

    const int tid  = threadIdx.x;
    const int warp = tid >> 5;
    const int lane = tid & 31;
    const int wm   = warp & 1;
    const int wn   = warp >> 1;
    const int m0   = blockIdx.y * 128;
    const int n0   = blockIdx.x * 128;

    const uint32_t sAh_b = smem_u32(sAh), sAl_b = smem_u32(sAl);
    const uint32_t sWh_b = smem_u32(sWh), sWl_b = smem_u32(sWl);

    float acc[4][4][4] = {};

    const int lrow = tid >> 1;
    const int lcol = (tid & 1) * 16;
    const uint32_t s_off = (uint32_t)(lrow * KSTR + lcol) * 2;

    const int fr = lane & 15;
    const int fc = (lane >> 4) * 8;
    const uint32_t a_off = (uint32_t)((wm * 64 + fr) * KSTR + fc) * 2;
    const uint32_t b_off = (uint32_t)((wn * 32 + fr) * KSTR + fc) * 2;

    for (int k0 = 0; k0 < DD; k0 += 32) {
        const size_t ga = (size_t)(m0 + lrow) * DD + k0 + lcol;
        const size_t gw = (size_t)(n0 + lrow) * DD + k0 + lcol;
        *(uint4*)((char*)sAh + s_off)      = *(const uint4*)(Ahi + ga);
        *(uint4*)((char*)sAh + s_off + 16) = *(const uint4*)(Ahi + ga + 8);
        *(uint4*)((char*)sAl + s_off)      = *(const uint4*)(Alo + ga);
        *(uint4*)((char*)sAl + s_off + 16) = *(const uint4*)(Alo + ga + 8);
        *(uint4*)((char*)sWh + s_off)      = *(const uint4*)(Whi + gw);
        *(uint4*)((char*)sWh + s_off + 16) = *(const uint4*)(Whi + gw + 8);
        *(uint4*)((char*)sWl + s_off)      = *(const uint4*)(Wlo + gw);
        *(uint4*)((char*)sWl + s_off + 16) = *(const uint4*)(Wlo + gw + 8);
        __syncthreads();

        #pragma unroll
        for (int ks = 0; ks < 2; ks++) {
            const uint32_t ko = (uint32_t)(ks * 16) * 2;
            uint32_t ah[4][4], al[4][4];
            #pragma unroll
            for (int im = 0; im < 4; im++) {
                const uint32_t ro = (uint32_t)(im * 16 * KSTR) * 2;
                ldmatrix_x4(ah[im], sAh_b + a_off + ro + ko);
                ldmatrix_x4(al[im], sAl_b + a_off + ro + ko);
            }
            uint32_t bh[4][2], bl[4][2];
            #pragma unroll
            for (int p = 0; p < 2; p++) {
                const uint32_t ro = (uint32_t)(p * 16 * KSTR) * 2;
                uint32_t t[4];
                ldmatrix_x4(t, sWh_b + b_off + ro + ko);
                bh[2*p][0] = t[0]; bh[2*p][1] = t[2];
                bh[2*p+1][0] = t[1]; bh[2*p+1][1] = t[3];
                ldmatrix_x4(t, sWl_b + b_off + ro + ko);
                bl[2*p][0] = t[0]; bl[2*p][1] = t[2];
                bl[2*p+1][0] = t[1]; bl[2*p+1][1] = t[3];
            }
            #pragma unroll
            for (int im = 0; im < 4; im++)
                #pragma unroll
                for (int in = 0; in < 4; in++) {
                    mma_bf16(acc[im][in], ah[im], bh[in]);
                    mma_bf16(acc[im][in], ah[im], bl[in]);
                    mma_bf16(acc[im][in], al[im], bh[in]);
                }
        }
        __syncthreads();
    }

    const int tr = lane >> 2;
    const int tc = (lane & 3) * 2;
    #pragma unroll
    for (int im = 0; im < 4; im++) {
        #pragma unroll
        for (int in = 0; in < 4; in++) {
            const int m = m0 + wm * 64 + im * 16 + tr;
            const int n = n0 + wn * 32 + in * 8 + tc;
            const float bx = bias[n], by = bias[n + 1];
            float2 v0 = make_float2(acc[im][in][0] + bx, acc[im][in][1] + by);
            float2 v1 = make_float2(acc[im][in][2] + bx, acc[im][in][3] + by);
            *(float2*)(C + (size_t)m * DD + n) = v0;
            *(float2*)(C + (size_t)(m + 8) * DD + n) = v1;
        }
    }
}

// ---------------------------------------------------------------------------
// HMMA flash attention (causal), fp16 tensor cores + fp32 softmax.
// Block: 128 q x one (b,h); 8 warps, warp owns 16 q rows. K-tile = 64 keys.
// Q fragments (hi/lo fp16, scale folded in) live in REGISTERS - staged once
// through the K smem region in two 64-row phases. Static smem 27.6 KB.
// QK^T: (qh+ql)*k  (2 MMAs);  P*V: p*(vh+vl)  (2 MMAs); P stays in regs.
// Smem rows padded to 72 halves (144B) -> conflict-free ldmatrix.
// ---------------------------------------------------------------------------
#define QSTR 72

__global__ __launch_bounds__(256) void attn_hmma(
    const float* __restrict__ Qp, const float* __restrict__ Kp,
    const float* __restrict__ Vp, float* __restrict__ Op)
{
    __shared__ __align__(16) __half Ks [64 * QSTR];   // keys  (key-major)
    __shared__ __align__(16) __half VhT[64 * QSTR];   // V hi  (d-major)
    __shared__ __align__(16) __half VlT[64 * QSTR];   // V lo  (d-major)

    const int tid  = threadIdx.x;
    const int warp = tid >> 5;
    const int lane = tid & 31;
    const int g    = lane >> 2;           // row group 0..7
    const int tg   = lane & 3;            // col pair 0..3

    const int qb = gridDim.x - 1 - blockIdx.x;   // heavy blocks first
    const int bh = blockIdx.y;
    const int b  = bh >> 4;
    const int h  = bh & 15;
    const size_t rowbase = (size_t)b * SS;
    const int col0 = h * DKK;

    const uint32_t Ks_b  = smem_u32(Ks);
    const uint32_t VhT_b = smem_u32(VhT), VlT_b = smem_u32(VlT);

    const int fr  = lane & 15;
    const int fc8 = (lane >> 4) * 8;

    // ---- stage Q (128 x 64) through smem in 2 phases; fragments -> regs ----
    // Phase p covers q rows p*64..p*64+63: hi into Ks, lo into VhT.
    uint32_t qh[4][4], ql[4][4];          // [kc][frag]
    #pragma unroll
    for (int p = 0; p < 2; p++) {
        const int lr = tid >> 2;          // 0..63 local row
        const int db = (tid & 3) * 16;    // 16-elem col chunk
        const float* src = Qp + (rowbase + (size_t)(qb*128 + p*64 + lr)) * DD + col0 + db;
        __half* dh = Ks  + lr * QSTR + db;
        __half* dl = VhT + lr * QSTR + db;
        #pragma unroll
        for (int i = 0; i < 4; i++) {
            float4 v = *(const float4*)(src + i*4);
            float f0 = v.x * 0.125f, f1 = v.y * 0.125f;
            float f2 = v.z * 0.125f, f3 = v.w * 0.125f;
            __half h0 = __float2half_rn(f0), h1 = __float2half_rn(f1);
            __half h2 = __float2half_rn(f2), h3 = __float2half_rn(f3);
            ((__half2*)(dh + i*4))[0] = __halves2half2(h0, h1);
            ((__half2*)(dh + i*4))[1] = __halves2half2(h2, h3);
            ((__half2*)(dl + i*4))[0] = __halves2half2(
                __float2half_rn(f0 - __half2float(h0)),
                __float2half_rn(f1 - __half2float(h1)));
            ((__half2*)(dl + i*4))[1] = __halves2half2(
                __float2half_rn(f2 - __half2float(h2)),
                __float2half_rn(f3 - __half2float(h3)));
        }
        __syncthreads();
        if ((warp >> 2) == p) {
            const int w2 = warp & 3;      // 0..3 within phase
            const uint32_t fo = (uint32_t)((w2*16 + fr) * QSTR + fc8) * 2;
            #pragma unroll
            for (int kc = 0; kc < 4; kc++) {
                ldmatrix_x4(qh[kc], Ks_b  + fo + (uint32_t)(kc*16)*2);
                ldmatrix_x4(ql[kc], VhT_b + fo + (uint32_t)(kc*16)*2);
            }
        }
        __syncthreads();
    }

    float m_run[2] = {-1e30f, -1e30f};
    float l_run[2] = {0.f, 0.f};
    float o[8][4] = {};

    const int kb_max = 2*qb + 1;
    for (int kb = 0; kb <= kb_max; kb++) {
        // ---- load K tile (key-major fp16) + V tile (transposed hi/lo) ----
        {
            const int kr = tid >> 2;
            const int db = (tid & 3) * 16;
            const float* ksrc = Kp + (rowbase + (size_t)kb*64 + kr) * DD + col0 + db;
            const float* vsrc = Vp + (rowbase + (size_t)kb*64 + kr) * DD + col0 + db;
            __half* kd = Ks + kr * QSTR + db;
            #pragma unroll
            for (int i = 0; i < 4; i++) {
                float4 v = *(const float4*)(ksrc + i*4);
                ((__half2*)(kd + i*4))[0] = __floats2half2_rn(v.x, v.y);
                ((__half2*)(kd + i*4))[1] = __floats2half2_rn(v.z, v.w);
            }
            #pragma unroll
            for (int i = 0; i < 4; i++) {
                float4 v = *(const float4*)(vsrc + i*4);
                float f[4] = {v.x, v.y, v.z, v.w};
                #pragma unroll
                for (int jj = 0; jj < 4; jj++) {
                    int d = db + i*4 + jj;
                    __half vh = __float2half_rn(f[jj]);
                    __half vl = __float2half_rn(f[jj] - __half2float(vh));
                    VhT[d * QSTR + kr] = vh;
                    VlT[d * QSTR + kr] = vl;
                }
            }
        }
        __syncthreads();

        // ---- S = Q K^T (scaled) ----
        float s[8][4] = {};
        #pragma unroll
        for (int kc = 0; kc < 4; kc++) {
            #pragma unroll
            for (int g2 = 0; g2 < 4; g2++) {
                uint32_t t[4];
                ldmatrix_x4(t, Ks_b + ((uint32_t)((g2*16 + fr) * QSTR + fc8) + kc*16) * 2);
                mma_f16(s[2*g2],   qh[kc], t[0], t[2]);
                mma_f16(s[2*g2],   ql[kc], t[0], t[2]);
                mma_f16(s[2*g2+1], qh[kc], t[1], t[3]);
                mma_f16(s[2*g2+1], ql[kc], t[1], t[3]);
            }
        }

        // ---- causal mask ----
        const int q0 = qb*128 + warp*16 + g;
        if (kb*64 + 63 > q0) {
            #pragma unroll
            for (int j = 0; j < 8; j++)
                #pragma unroll
                for (int e = 0; e < 4; e++) {
                    int kg = kb*64 + j*8 + tg*2 + (e & 1);
                    int qg = q0 + (e >> 1) * 8;
                    if (kg > qg) s[j][e] = -1e30f;
                }
        }

        // ---- online softmax (rows g and g+8; reduce over 4 lanes) ----
        float fac[2];
        #pragma unroll
        for (int hf = 0; hf < 2; hf++) {
            float tm = -1e30f;
            #pragma unroll
            for (int j = 0; j < 8; j++)
                tm = fmaxf(tm, fmaxf(s[j][2*hf], s[j][2*hf+1]));
            tm = fmaxf(tm, __shfl_xor_sync(0xffffffffu, tm, 1));
            tm = fmaxf(tm, __shfl_xor_sync(0xffffffffu, tm, 2));
            float mn = fmaxf(m_run[hf], tm);
            fac[hf]  = __expf(m_run[hf] - mn);
            m_run[hf] = mn;
            float rs = 0.f;
            #pragma unroll
            for (int j = 0; j < 8; j++) {
                float p0 = __expf(s[j][2*hf]   - mn);
                float p1 = __expf(s[j][2*hf+1] - mn);
                s[j][2*hf] = p0; s[j][2*hf+1] = p1;
                rs += p0 + p1;
            }
            rs += __shfl_xor_sync(0xffffffffu, rs, 1);
            rs += __shfl_xor_sync(0xffffffffu, rs, 2);
            l_run[hf] = l_run[hf] * fac[hf] + rs;
        }
        #pragma unroll
        for (int j = 0; j < 8; j++) {
            o[j][0] *= fac[0]; o[j][1] *= fac[0];
            o[j][2] *= fac[1]; o[j][3] *= fac[1];
        }

        // ---- O += P V  (P from S fragments, fp16) ----
        #pragma unroll
        for (int pk = 0; pk < 4; pk++) {
            uint32_t ap[4];
            __half2 h0 = __floats2half2_rn(s[2*pk][0],   s[2*pk][1]);
            __half2 h1 = __floats2half2_rn(s[2*pk][2],   s[2*pk][3]);
            __half2 h2 = __floats2half2_rn(s[2*pk+1][0], s[2*pk+1][1]);
            __half2 h3 = __floats2half2_rn(s[2*pk+1][2], s[2*pk+1][3]);
            ap[0] = *(uint32_t*)&h0; ap[1] = *(uint32_t*)&h1;
            ap[2] = *(uint32_t*)&h2; ap[3] = *(uint32_t*)&h3;
            const uint32_t vo = ((uint32_t)(fr * QSTR + fc8) + pk*16) * 2;
            #pragma unroll
            for (int g2 = 0; g2 < 4; g2++) {
                uint32_t t[4];
                ldmatrix_x4(t, VhT_b + vo + (uint32_t)(g2*16*QSTR)*2);
                mma_f16(o[2*g2],   ap, t[0], t[2]);
                mma_f16(o[2*g2+1], ap, t[1], t[3]);
                ldmatrix_x4(t, VlT_b + vo + (uint32_t)(g2*16*QSTR)*2);
                mma_f16(o[2*g2],   ap, t[0], t[2]);
                mma_f16(o[2*g2+1], ap, t[1], t[3]);
            }
        }
        __syncthreads();   // all warps done with Ks/V before next load
    }

    // ---- epilogue ----
    const float inv0 = 1.f / l_run[0];
    const float inv1 = 1.f / l_run[1];
    const size_t q0 = rowbase + (size_t)qb*128 + warp*16 + g;
    #pragma unroll
    for (int j = 0; j < 8; j++) {
        const int d = col0 + j*8 + tg*2;
        *(float2*)(Op + q0 * DD + d)       = make_float2(o[j][0]*inv0, o[j][1]*inv0);
        *(float2*)(Op + (q0 + 8) * DD + d) = make_float2(o[j][2]*inv1, o[j][3]*inv1);
    }
}

// ---------------------------------------------------------------------------
// Launch. Inputs (metadata order): q,k,v,mask,wq,bq,wk,bk,wv,bv,wo,bo
// NOTE: no runtime API calls here besides symbol lookups + launches
// (kernel_launch runs under graph capture).
// ---------------------------------------------------------------------------
extern "C" void kernel_launch(void* const* d_in, const int* in_sizes, int n_in,
                              void* d_out, int out_size)
{
    const float* q  = (const float*)d_in[0];
    const float* k  = (const float*)d_in[1];
    const float* v  = (const float*)d_in[2];
    const float* wq = (const float*)d_in[4];
    const float* bq = (const float*)d_in[5];
    const float* wk = (const float*)d_in[6];
    const float* bk = (const float*)d_in[7];
    const float* wv = (const float*)d_in[8];
    const float* bv = (const float*)d_in[9];
    const float* wo = (const float*)d_in[10];
    const float* bo = (const float*)d_in[11];

    float *Qp, *Kp, *Vp, *Opp;
    __nv_bfloat16 *hi, *lo;
    cudaGetSymbolAddress((void**)&Qp,  g_Q);
    cudaGetSymbolAddress((void**)&Kp,  g_K);
    cudaGetSymbolAddress((void**)&Vp,  g_V);
    cudaGetSymbolAddress((void**)&Opp, g_O);
    cudaGetSymbolAddress((void**)&hi,  g_hi);
    cudaGetSymbolAddress((void**)&lo,  g_lo);

    const int nin4 = (int)(ELEMS_IN / 4);
    const int nw4  = (int)(ELEMS_W / 4);

    split_bf16<<<nin4 / 256, 256>>>(q,  hi + OFF_Q,  lo + OFF_Q,  nin4);
    split_bf16<<<nin4 / 256, 256>>>(k,  hi + OFF_K,  lo + OFF_K,  nin4);
    split_bf16<<<nin4 / 256, 256>>>(v,  hi + OFF_V,  lo + OFF_V,  nin4);
    split_bf16<<<nw4  / 256, 256>>>(wq, hi + OFF_WQ, lo + OFF_WQ, nw4);
    split_bf16<<<nw4  / 256, 256>>>(wk, hi + OFF_WK, lo + OFF_WK, nw4);
    split_bf16<<<nw4  / 256, 256>>>(wv, hi + OFF_WV, lo + OFF_WV, nw4);
    split_bf16<<<nw4  / 256, 256>>>(wo, hi + OFF_WO, lo + OFF_WO, nw4);

    dim3 gemmGrid(DD / 128, MM / 128);   // (8, 32)
    gemm_hmma<<<gemmGrid, 256>>>(hi + OFF_Q, lo + OFF_Q, hi + OFF_WQ, lo + OFF_WQ, bq, Qp);
    gemm_hmma<<<gemmGrid, 256>>>(hi + OFF_K, lo + OFF_K, hi + OFF_WK, lo + OFF_WK, bk, Kp);
    gemm_hmma<<<gemmGrid, 256>>>(hi + OFF_V, lo + OFF_V, hi + OFF_WV, lo + OFF_WV, bv, Vp);

    dim3 attnGrid(SS / 128, BB * HH);    // (16, 32)
    attn_hmma<<<attnGrid, 256>>>(Qp, Kp, Vp, Opp);

    split_bf16<<<nin4 / 256, 256>>>(Opp, hi + OFF_O, lo + OFF_O, nin4);
    gemm_hmma<<<gemmGrid, 256>>>(hi + OFF_O, lo + OFF_O, hi + OFF_WO, lo + OFF_WO, bo, (float*)d_out);
}